// round 1
// baseline (speedup 1.0000x reference)
#include <cuda_runtime.h>

// ---------------- problem constants ----------------
#define NL   16
#define DM   1024
#define NH   16
#define NKV  8
#define DH   128
#define SEQ  4096
#define FF   4096
#define VOC  32000

#define NP_QKV 16
#define NP_WO  16
#define NP_GU  16
#define NP_WD  16
#define NP_LM  4

// ---------------- scratch (device globals; no allocs allowed) ----------------
__device__ __align__(16) float g_xA[DM];
__device__ __align__(16) float g_xB[DM];
__device__ __align__(16) float g_qkv_part[NP_QKV][NH*DH + 2*NKV*DH];  // 4096 cols
__device__ __align__(16) float g_o_part[NP_WO][DM];
__device__ __align__(16) float g_gu_part[NP_GU][2*FF];
__device__ __align__(16) float g_d_part[NP_WD][DM];
__device__ __align__(16) float g_lm_part[NP_LM][VOC];
__device__ float g_attn_m[NKV][16][2];
__device__ float g_attn_l[NKV][16][2];
__device__ __align__(16) float g_attn_o[NKV][16][2][DH];
__device__ float g_amax_val[128];
__device__ int   g_amax_idx[128];

// ---------------- KV cache copy-out ----------------
__global__ void k_copy(const float* __restrict__ a, const float* __restrict__ b,
                       float* __restrict__ oa, float* __restrict__ ob)
{
    const long N = (long)NL * NKV * SEQ * DH;   // 67108864 per tensor
    long i = (long)blockIdx.x * blockDim.x + threadIdx.x;
    long stride = (long)gridDim.x * blockDim.x;
    for (; i < N; i += stride) { oa[i] = a[i]; ob[i] = b[i]; }
}

// ---------------- shared prologue: x = xin + sum(parts); rstd of rmsnorm ----
// 256 threads. Fills sh_x[DM]; block(0,0) optionally writes x to xout.
__device__ __forceinline__ float prologue256(const float* __restrict__ xin,
                                             const float* __restrict__ parts, int np,
                                             float* __restrict__ xout,
                                             float* sh_x, float* sh_red)
{
    int tid = threadIdx.x;
    float4 xv = reinterpret_cast<const float4*>(xin)[tid];
    for (int i = 0; i < np; ++i) {
        float4 pv = reinterpret_cast<const float4*>(parts + (long)i * DM)[tid];
        xv.x += pv.x; xv.y += pv.y; xv.z += pv.z; xv.w += pv.w;
    }
    reinterpret_cast<float4*>(sh_x)[tid] = xv;
    if (xout && blockIdx.x == 0 && blockIdx.y == 0)
        reinterpret_cast<float4*>(xout)[tid] = xv;
    float ss = xv.x*xv.x + xv.y*xv.y + xv.z*xv.z + xv.w*xv.w;
    #pragma unroll
    for (int o = 16; o > 0; o >>= 1) ss += __shfl_down_sync(0xffffffffu, ss, o);
    if ((tid & 31) == 0) sh_red[tid >> 5] = ss;
    __syncthreads();
    if (tid == 0) {
        float t = 0.f;
        #pragma unroll
        for (int i = 0; i < 8; ++i) t += sh_red[i];
        sh_red[0] = rsqrtf(t * (1.0f / DM) + 1e-6f);
    }
    __syncthreads();
    return sh_red[0];
}

// ---------------- QKV GEMV (consumes prev-layer Wd partials) ----------------
// grid (4, NP_QKV), 256 thr. cols: [0,2048)=Wq, [2048,3072)=Wk, [3072,4096)=Wv
__global__ void __launch_bounds__(256) k_qkv(
    const float* __restrict__ embed, const int* __restrict__ ids,
    const float* __restrict__ lnw,
    const float* __restrict__ Wq, const float* __restrict__ Wk,
    const float* __restrict__ Wv, int first)
{
    __shared__ __align__(16) float sh_x[DM];
    __shared__ float sh_n[64];
    __shared__ float sh_red[8];
    const float* xin = first ? (embed + (long)ids[0] * DM) : g_xA;
    const float* parts = &g_d_part[0][0];
    int np = first ? 0 : NP_WD;
    float rstd = prologue256(xin, parts, np, g_xB, sh_x, sh_red);

    int tid = threadIdx.x;
    int d0 = blockIdx.y * 64;
    if (tid < 64) sh_n[tid] = sh_x[d0 + tid] * rstd * lnw[d0 + tid];
    __syncthreads();

    int j = blockIdx.x * 1024 + tid * 4;
    const float* W; int cols, jj;
    if (j < NH*DH)            { W = Wq; cols = NH*DH;  jj = j; }
    else if (j < NH*DH + NKV*DH) { W = Wk; cols = NKV*DH; jj = j - NH*DH; }
    else                      { W = Wv; cols = NKV*DH; jj = j - NH*DH - NKV*DH; }
    const float* p = W + (long)d0 * cols + jj;
    float4 acc = {0.f,0.f,0.f,0.f};
    #pragma unroll 8
    for (int r = 0; r < 64; ++r) {
        float nv = sh_n[r];
        float4 w = *reinterpret_cast<const float4*>(p);
        acc.x += nv*w.x; acc.y += nv*w.y; acc.z += nv*w.z; acc.w += nv*w.w;
        p += cols;
    }
    *reinterpret_cast<float4*>(&g_qkv_part[blockIdx.y][j]) = acc;
}

// ---------------- attention: split-S flash-decode partials -----------------
// grid (16 chunks, NKV), 256 thr. Also ropes q,k from qkv partials and writes
// the new cache row (roped k, raw v) into d_out.
__global__ void __launch_bounds__(256) k_attn(
    const float* __restrict__ pk, const float* __restrict__ pv,
    const int* __restrict__ stepp, const int* __restrict__ plen,
    int layer, float* __restrict__ ok, float* __restrict__ ov)
{
    __shared__ __align__(16) float sh_q[2][DH];
    __shared__ __align__(16) float sh_k[DH];
    __shared__ __align__(16) float sh_v[DH];
    __shared__ float sh_s[2][256];
    __shared__ float sh_red[16];
    __shared__ float sh_m[2];

    int pos = stepp[0] + plen[0];
    int kv = blockIdx.y, chunk = blockIdx.x;
    int s0 = chunk << 8;
    int tid = threadIdx.x;
    if (s0 > pos) {
        if (tid < 2) g_attn_l[kv][chunk][tid] = 0.f;
        return;
    }
    int smax = min(pos, s0 + 255);
    int count = smax - s0 + 1;
    bool haspos = (chunk == (pos >> 8));

    // reduce raw q (and k,v if this chunk owns row pos) from partials
    {
        int h = tid >> 7, d = tid & 127;
        float a = 0.f;
        #pragma unroll
        for (int i = 0; i < NP_QKV; ++i) a += g_qkv_part[i][(kv*2 + h)*DH + d];
        sh_q[h][d] = a;
    }
    if (haspos) {
        int d = tid & 127;
        int off = (tid < 128) ? (NH*DH + kv*DH + d) : (NH*DH + NKV*DH + kv*DH + d);
        float a = 0.f;
        #pragma unroll
        for (int i = 0; i < NP_QKV; ++i) a += g_qkv_part[i][off];
        if (tid < 128) sh_k[d] = a; else sh_v[d] = a;
    }
    __syncthreads();

    // RoPE (q scaled by 1/sqrt(DH); k unscaled)
    const float SCALE = 0.08838834764831845f;
    if (tid < 128) {
        int h = tid >> 6, i = tid & 63;
        float inv = expf(-(float)i * 0.14391156516533442f);  // ln(10000)/64
        float ang = (float)pos * inv;
        float c = cosf(ang), s = sinf(ang);
        float x1 = sh_q[h][i], x2 = sh_q[h][i + 64];
        sh_q[h][i]      = (x1*c - x2*s) * SCALE;
        sh_q[h][i + 64] = (x2*c + x1*s) * SCALE;
        if (haspos && h == 0) {
            float k1 = sh_k[i], k2 = sh_k[i + 64];
            sh_k[i]      = k1*c - k2*s;
            sh_k[i + 64] = k2*c + k1*s;
        }
    }
    __syncthreads();

    long rowbase = (((long)layer * NKV + kv) * SEQ + pos) * DH;
    if (haspos && tid < 128) {
        ok[rowbase + tid] = sh_k[tid];
        ov[rowbase + tid] = sh_v[tid];
    }

    // scores: warp per s (4 dims/lane), two q-heads
    int warp = tid >> 5, lane = tid & 31;
    float4 q0 = reinterpret_cast<const float4*>(sh_q[0])[lane];
    float4 q1 = reinterpret_cast<const float4*>(sh_q[1])[lane];
    long kbase = (((long)layer * NKV + kv) * SEQ) * DH;
    for (int it = 0; it < 32; ++it) {
        int si = s0 + (it << 3) + warp;
        int sl = si - s0;
        if (si <= smax) {
            float4 kk;
            if (si == pos) kk = reinterpret_cast<const float4*>(sh_k)[lane];
            else kk = *reinterpret_cast<const float4*>(pk + kbase + (long)si*DH + lane*4);
            float d0v = q0.x*kk.x + q0.y*kk.y + q0.z*kk.z + q0.w*kk.w;
            float d1v = q1.x*kk.x + q1.y*kk.y + q1.z*kk.z + q1.w*kk.w;
            #pragma unroll
            for (int o = 16; o > 0; o >>= 1) {
                d0v += __shfl_down_sync(0xffffffffu, d0v, o);
                d1v += __shfl_down_sync(0xffffffffu, d1v, o);
            }
            if (lane == 0) { sh_s[0][sl] = d0v; sh_s[1][sl] = d1v; }
        } else if (lane == 0) {
            sh_s[0][sl] = -1e30f; sh_s[1][sl] = -1e30f;
        }
    }
    __syncthreads();

    // softmax (chunk-local, saved as (m, l, unnormalized acc))
    float v0 = sh_s[0][tid], v1 = sh_s[1][tid];
    float a0 = v0, a1 = v1;
    #pragma unroll
    for (int o = 16; o > 0; o >>= 1) {
        a0 = fmaxf(a0, __shfl_down_sync(0xffffffffu, a0, o));
        a1 = fmaxf(a1, __shfl_down_sync(0xffffffffu, a1, o));
    }
    if ((tid & 31) == 0) { sh_red[warp] = a0; sh_red[8 + warp] = a1; }
    __syncthreads();
    if (tid == 0) {
        float m = -1e30f;
        for (int i = 0; i < 8; ++i) m = fmaxf(m, sh_red[i]);
        sh_m[0] = m;
        m = -1e30f;
        for (int i = 0; i < 8; ++i) m = fmaxf(m, sh_red[8 + i]);
        sh_m[1] = m;
    }
    __syncthreads();
    float p0 = expf(v0 - sh_m[0]);
    float p1 = expf(v1 - sh_m[1]);
    sh_s[0][tid] = p0; sh_s[1][tid] = p1;
    float s0v = p0, s1v = p1;
    #pragma unroll
    for (int o = 16; o > 0; o >>= 1) {
        s0v += __shfl_down_sync(0xffffffffu, s0v, o);
        s1v += __shfl_down_sync(0xffffffffu, s1v, o);
    }
    if ((tid & 31) == 0) { sh_red[warp] = s0v; sh_red[8 + warp] = s1v; }
    __syncthreads();
    if (tid == 0) {
        float l0 = 0.f, l1 = 0.f;
        for (int i = 0; i < 8; ++i) { l0 += sh_red[i]; l1 += sh_red[8 + i]; }
        g_attn_m[kv][chunk][0] = sh_m[0]; g_attn_m[kv][chunk][1] = sh_m[1];
        g_attn_l[kv][chunk][0] = l0;      g_attn_l[kv][chunk][1] = l1;
    }
    __syncthreads();

    // AV
    int h = tid >> 7, d = tid & 127;
    int nglob = haspos ? count - 1 : count;
    const float* pvp = pv + kbase + (long)s0 * DH + d;
    float acc = 0.f;
    #pragma unroll 4
    for (int s = 0; s < nglob; ++s) acc += sh_s[h][s] * pvp[(long)s * DH];
    if (haspos) acc += sh_s[h][count - 1] * sh_v[d];
    g_attn_o[kv][chunk][h][d] = acc;
}

// ---------------- Wo GEMV (combines attn partials for its 128-row slice) ---
// grid (1,16), 512 thr. blockIdx.y = global head p.
__global__ void __launch_bounds__(512) k_wo(const float* __restrict__ Wo)
{
    __shared__ __align__(16) float sh_a[DH];
    __shared__ float sh_m16[16], sh_l16[16], sh_w[16], sh_iden[1];
    int p = blockIdx.y;
    int kv = p >> 1, h = p & 1;
    int tid = threadIdx.x;
    if (tid < 16) { sh_m16[tid] = g_attn_m[kv][tid][h]; sh_l16[tid] = g_attn_l[kv][tid][h]; }
    __syncthreads();
    if (tid == 0) {
        float M = -1e30f;
        for (int c = 0; c < 16; ++c) if (sh_l16[c] > 0.f) M = fmaxf(M, sh_m16[c]);
        float den = 0.f;
        for (int c = 0; c < 16; ++c) {
            float w = (sh_l16[c] > 0.f) ? expf(sh_m16[c] - M) : 0.f;
            sh_w[c] = w; den += w * sh_l16[c];
        }
        sh_iden[0] = 1.f / den;
    }
    __syncthreads();
    if (tid < 128) {
        float num = 0.f;
        #pragma unroll
        for (int c = 0; c < 16; ++c) {
            float w = sh_w[c];
            if (w != 0.f) num += w * g_attn_o[kv][c][h][tid];
        }
        sh_a[tid] = num * sh_iden[0];
    }
    __syncthreads();
    int j = tid * 2;
    const float* pw = Wo + (long)p * DH * DM + j;
    float2 acc = {0.f, 0.f};
    #pragma unroll 8
    for (int r = 0; r < DH; ++r) {
        float a = sh_a[r];
        float2 w = *reinterpret_cast<const float2*>(pw + (long)r * DM);
        acc.x += a * w.x; acc.y += a * w.y;
    }
    *reinterpret_cast<float2*>(&g_o_part[p][j]) = acc;
}

// ---------------- gate/up GEMV (consumes Wo partials) ----------------------
// grid (8, NP_GU), 256 thr.
__global__ void __launch_bounds__(256) k_gateup(
    const float* __restrict__ lnw,
    const float* __restrict__ Wg, const float* __restrict__ Wu)
{
    __shared__ __align__(16) float sh_x[DM];
    __shared__ float sh_n[64];
    __shared__ float sh_red[8];
    float rstd = prologue256(g_xB, &g_o_part[0][0], NP_WO, g_xA, sh_x, sh_red);
    int tid = threadIdx.x;
    int d0 = blockIdx.y * 64;
    if (tid < 64) sh_n[tid] = sh_x[d0 + tid] * rstd * lnw[d0 + tid];
    __syncthreads();
    int j = blockIdx.x * 1024 + tid * 4;
    const float* W; int jj;
    if (j < FF) { W = Wg; jj = j; } else { W = Wu; jj = j - FF; }
    const float* p = W + (long)d0 * FF + jj;
    float4 acc = {0.f,0.f,0.f,0.f};
    #pragma unroll 8
    for (int r = 0; r < 64; ++r) {
        float nv = sh_n[r];
        float4 w = *reinterpret_cast<const float4*>(p);
        acc.x += nv*w.x; acc.y += nv*w.y; acc.z += nv*w.z; acc.w += nv*w.w;
        p += FF;
    }
    *reinterpret_cast<float4*>(&g_gu_part[blockIdx.y][j]) = acc;
}

// ---------------- Wd GEMV (silu(gate)*up for its 256-row slice) ------------
// grid (1, NP_WD), 512 thr.
__global__ void __launch_bounds__(512) k_wd(const float* __restrict__ Wd)
{
    __shared__ float sh_h[256];
    int r0 = blockIdx.y * 256;
    int tid = threadIdx.x;
    if (tid < 256) {
        float g = 0.f, u = 0.f;
        #pragma unroll
        for (int i = 0; i < NP_GU; ++i) {
            g += g_gu_part[i][r0 + tid];
            u += g_gu_part[i][FF + r0 + tid];
        }
        sh_h[tid] = (g / (1.f + expf(-g))) * u;
    }
    __syncthreads();
    int j = tid * 2;
    const float* pw = Wd + (long)r0 * DM + j;
    float2 acc = {0.f, 0.f};
    #pragma unroll 8
    for (int r = 0; r < 256; ++r) {
        float a = sh_h[r];
        float2 w = *reinterpret_cast<const float2*>(pw + (long)r * DM);
        acc.x += a * w.x; acc.y += a * w.y;
    }
    *reinterpret_cast<float2*>(&g_d_part[blockIdx.y][j]) = acc;
}

// ---------------- LM head GEMV (final norm) --------------------------------
// grid (32, NP_LM), 256 thr.
__global__ void __launch_bounds__(256) k_lm(
    const float* __restrict__ lnf, const float* __restrict__ Wlm)
{
    __shared__ __align__(16) float sh_x[DM];
    __shared__ float sh_n[256];
    __shared__ float sh_red[8];
    float rstd = prologue256(g_xA, &g_d_part[0][0], NP_WD, nullptr, sh_x, sh_red);
    int tid = threadIdx.x;
    int d0 = blockIdx.y * 256;
    sh_n[tid] = sh_x[d0 + tid] * rstd * lnf[d0 + tid];
    __syncthreads();
    int j = blockIdx.x * 1024 + tid * 4;
    if (j < VOC) {
        const float* p = Wlm + (long)d0 * VOC + j;
        float4 acc = {0.f,0.f,0.f,0.f};
        #pragma unroll 8
        for (int r = 0; r < 256; ++r) {
            float nv = sh_n[r];
            float4 w = *reinterpret_cast<const float4*>(p);
            acc.x += nv*w.x; acc.y += nv*w.y; acc.z += nv*w.z; acc.w += nv*w.w;
            p += VOC;
        }
        *reinterpret_cast<float4*>(&g_lm_part[blockIdx.y][j]) = acc;
    }
}

// ---------------- argmax ---------------------------------------------------
__global__ void __launch_bounds__(256) k_amax1()
{
    __shared__ float sv[256];
    __shared__ int   si[256];
    int t = threadIdx.x;
    int j = blockIdx.x * 256 + t;
    float v = 0.f;
    #pragma unroll
    for (int i = 0; i < NP_LM; ++i) v += g_lm_part[i][j];
    sv[t] = v; si[t] = j;
    __syncthreads();
    for (int o = 128; o > 0; o >>= 1) {
        if (t < o) {
            float v2 = sv[t + o]; int i2 = si[t + o];
            if (v2 > sv[t] || (v2 == sv[t] && i2 < si[t])) { sv[t] = v2; si[t] = i2; }
        }
        __syncthreads();
    }
    if (t == 0) { g_amax_val[blockIdx.x] = sv[0]; g_amax_idx[blockIdx.x] = si[0]; }
}

__global__ void __launch_bounds__(128) k_amax2(float* __restrict__ out)
{
    __shared__ float sv[128];
    __shared__ int   si[128];
    int t = threadIdx.x;
    if (t < 125) { sv[t] = g_amax_val[t]; si[t] = g_amax_idx[t]; }
    else         { sv[t] = -1e38f;        si[t] = 0x7fffffff; }
    __syncthreads();
    for (int o = 64; o > 0; o >>= 1) {
        if (t < o) {
            float v2 = sv[t + o]; int i2 = si[t + o];
            if (v2 > sv[t] || (v2 == sv[t] && i2 < si[t])) { sv[t] = v2; si[t] = i2; }
        }
        __syncthreads();
    }
    if (t == 0) out[0] = (float)si[0];
}

// ---------------- launch ---------------------------------------------------
extern "C" void kernel_launch(void* const* d_in, const int* in_sizes, int n_in,
                              void* d_out, int out_size)
{
    const int*   ids  = (const int*)  d_in[0];
    const int*   step = (const int*)  d_in[1];
    const int*   plen = (const int*)  d_in[2];
    const float* pk   = (const float*)d_in[3];
    const float* pv   = (const float*)d_in[4];
    const float* emb  = (const float*)d_in[5];
    const float* Wq   = (const float*)d_in[6];
    const float* Wk   = (const float*)d_in[7];
    const float* Wv   = (const float*)d_in[8];
    const float* Wo   = (const float*)d_in[9];
    const float* Wg   = (const float*)d_in[10];
    const float* Wu   = (const float*)d_in[11];
    const float* Wd   = (const float*)d_in[12];
    const float* ln1  = (const float*)d_in[13];
    const float* ln2  = (const float*)d_in[14];
    const float* lnf  = (const float*)d_in[15];
    const float* Wlm  = (const float*)d_in[16];

    float* out = (float*)d_out;
    const long CACHE = (long)NL * NKV * SEQ * DH;
    float* ok = out + 1;
    float* ov = out + 1 + CACHE;

    k_copy<<<2048, 256>>>(pk, pv, ok, ov);

    for (int l = 0; l < NL; ++l) {
        k_qkv<<<dim3(4, NP_QKV), 256>>>(
            emb, ids, ln1 + (long)l * DM,
            Wq + (long)l * DM * NH * DH,
            Wk + (long)l * DM * NKV * DH,
            Wv + (long)l * DM * NKV * DH,
            l == 0);
        k_attn<<<dim3(16, NKV), 256>>>(pk, pv, step, plen, l, ok, ov);
        k_wo<<<dim3(1, 16), 512>>>(Wo + (long)l * NH * DH * DM);
        k_gateup<<<dim3(8, NP_GU), 256>>>(
            ln2 + (long)l * DM,
            Wg + (long)l * DM * FF,
            Wu + (long)l * DM * FF);
        k_wd<<<dim3(1, NP_WD), 512>>>(Wd + (long)l * FF * DM);
    }

    k_lm<<<dim3(32, NP_LM), 256>>>(lnf, Wlm);
    k_amax1<<<125, 256>>>();
    k_amax2<<<1, 128>>>(out);
}

// round 7
// speedup vs baseline: 1.2885x; 1.2885x over previous
#include <cuda_runtime.h>

// ---------------- problem constants ----------------
#define NL   16
#define DM   1024
#define NH   16
#define NKV  8
#define DH   128
#define SEQ  4096
#define FF   4096
#define VOC  32000

#define NPQ  16    // qkv row splits (rows of 64)
#define NPO  64    // wo row splits  (rows of 32)
#define NPG  32    // gate/up row splits (rows of 32)
#define NPD  64    // wd row splits  (rows of 64)
#define NPL  8     // lm row splits  (rows of 128)
#define NCH  32    // attention chunks of 128

// ---------------- scratch ----------------
__device__ __align__(16) float g_x[DM];
__device__ __align__(16) float g_n[DM];
__device__ __align__(16) float g_qkv_part[NPQ][NH*DH + 2*NKV*DH];
__device__ __align__(16) float g_q[NH*DH];
__device__ __align__(16) float g_knew[NKV][DH];
__device__ __align__(16) float g_vnew[NKV][DH];
__device__ float g_attn_m[NKV][NCH][2];
__device__ float g_attn_l[NKV][NCH][2];
__device__ __align__(16) float g_attn_o[NKV][NCH][2][DH];
__device__ __align__(16) float g_o_part[NPO][DM];
__device__ __align__(16) float g_gu_part[NPG][2*FF];
__device__ __align__(16) float g_d_part[NPD][DM];
__device__ __align__(16) float g_lm_part[NPL][VOC];
__device__ float g_amax_val[128];
__device__ int   g_amax_idx[128];

__device__ __forceinline__ void fma4(float4& acc, float a, const float4& w) {
    acc.x += a * w.x; acc.y += a * w.y; acc.z += a * w.z; acc.w += a * w.w;
}

// ---------------- KV cache copy ----------------
// dest = out+1 floats (16B-misaligned by 4B). Dest-aligned float4 stores with
// two aligned float4 loads recombined. Head(3)/tail(1) elements scalar.
__global__ void k_copy(const float* __restrict__ a, const float* __restrict__ b,
                       float* __restrict__ oa, float* __restrict__ ob)
{
    const long N = (long)NL * NKV * SEQ * DH;     // 67108864
    const long T = (N - 3) >> 2;                  // dest quads
    long t = (long)blockIdx.x * blockDim.x + threadIdx.x;
    long st = (long)gridDim.x * blockDim.x;
    const float4* a4 = (const float4*)a;
    const float4* b4 = (const float4*)b;
    float4* oa4 = (float4*)(oa + 3);
    float4* ob4 = (float4*)(ob + 3);
    for (; t < T; t += st) {
        float4 A = a4[t], B = a4[t + 1];
        float4 r; r.x = A.w; r.y = B.x; r.z = B.y; r.w = B.z;
        __stcs(oa4 + t, r);
        A = b4[t]; B = b4[t + 1];
        r.x = A.w; r.y = B.x; r.z = B.y; r.w = B.z;
        __stcs(ob4 + t, r);
    }
    if (blockIdx.x == 0 && threadIdx.x < 4) {
        long i = threadIdx.x < 3 ? (long)threadIdx.x : N - 1;
        oa[i] = a[i]; ob[i] = b[i];
    }
}

// ---------------- reduce partials + residual + rmsnorm ----------------
// 1 block, 256 threads. mode 0: x = embed row. mode 1: x = g_x + sum d_part.
// mode 2: x = g_x + sum o_part. Writes g_x and g_n = rmsnorm(x)*lnw.
__global__ void __launch_bounds__(256) k_rn(
    const float* __restrict__ lnw, int mode,
    const float* __restrict__ embed, const int* __restrict__ ids)
{
    __shared__ float red[8];
    int tid = threadIdx.x;
    float4 xv;
    if (mode == 0) xv = ((const float4*)(embed + (long)ids[0] * DM))[tid];
    else           xv = ((const float4*)g_x)[tid];
    if (mode == 1) {
        #pragma unroll 8
        for (int i = 0; i < NPD; ++i) {
            float4 p = ((const float4*)g_d_part[i])[tid];
            xv.x += p.x; xv.y += p.y; xv.z += p.z; xv.w += p.w;
        }
    } else if (mode == 2) {
        #pragma unroll 8
        for (int i = 0; i < NPO; ++i) {
            float4 p = ((const float4*)g_o_part[i])[tid];
            xv.x += p.x; xv.y += p.y; xv.z += p.z; xv.w += p.w;
        }
    }
    ((float4*)g_x)[tid] = xv;
    float ss = xv.x*xv.x + xv.y*xv.y + xv.z*xv.z + xv.w*xv.w;
    #pragma unroll
    for (int o = 16; o > 0; o >>= 1) ss += __shfl_down_sync(0xffffffffu, ss, o);
    if ((tid & 31) == 0) red[tid >> 5] = ss;
    __syncthreads();
    if (tid == 0) {
        float t = 0.f;
        #pragma unroll
        for (int i = 0; i < 8; ++i) t += red[i];
        red[0] = rsqrtf(t * (1.0f / DM) + 1e-6f);
    }
    __syncthreads();
    float rstd = red[0];
    float4 lw = ((const float4*)lnw)[tid];
    float4 nv = { xv.x*rstd*lw.x, xv.y*rstd*lw.y, xv.z*rstd*lw.z, xv.w*rstd*lw.w };
    ((float4*)g_n)[tid] = nv;
}

// ---------------- QKV GEMV ----------------
// grid (4 coltiles of 1024, NPQ rowslices of 64), 256 thr.
__global__ void __launch_bounds__(256) k_qkv(
    const float* __restrict__ Wq, const float* __restrict__ Wk,
    const float* __restrict__ Wv)
{
    __shared__ float sh_n[64];
    int tid = threadIdx.x;
    int r0 = blockIdx.y * 64;
    if (tid < 64) sh_n[tid] = g_n[r0 + tid];
    __syncthreads();
    int j = blockIdx.x * 1024 + tid * 4;
    const float* W; int cols, jj;
    if (j < 2048)      { W = Wq; cols = 2048; jj = j; }
    else if (j < 3072) { W = Wk; cols = 1024; jj = j - 2048; }
    else               { W = Wv; cols = 1024; jj = j - 3072; }
    const float* p = W + (long)r0 * cols + jj;
    float4 acc = {0.f,0.f,0.f,0.f};
    #pragma unroll 8
    for (int r = 0; r < 64; ++r) {
        float a = sh_n[r];
        float4 w = *(const float4*)p;
        fma4(acc, a, w);
        p += cols;
    }
    *(float4*)&g_qkv_part[blockIdx.y][j] = acc;
}

// ---------------- reduce qkv partials, rope, write cache row, publish q ----
// 1 block, 512 threads. Publishes roped q (g_q), roped k (g_knew), raw v
// (g_vnew), and writes the new cache row into the output cache.
__global__ void __launch_bounds__(512) k_qkvr(
    const int* __restrict__ stepp, const int* __restrict__ plen, int layer,
    float* __restrict__ ok, float* __restrict__ ov)
{
    __shared__ __align__(16) float sh[4096];
    int tid = threadIdx.x;
    int pos = stepp[0] + plen[0];
    int c0 = tid * 8;
    float4 a0 = {0,0,0,0}, a1 = {0,0,0,0};
    #pragma unroll 4
    for (int i = 0; i < NPQ; ++i) {
        const float4* p = (const float4*)&g_qkv_part[i][c0];
        float4 u = p[0], v = p[1];
        a0.x+=u.x; a0.y+=u.y; a0.z+=u.z; a0.w+=u.w;
        a1.x+=v.x; a1.y+=v.y; a1.z+=v.z; a1.w+=v.w;
    }
    *(float4*)&sh[c0] = a0;
    *(float4*)&sh[c0 + 4] = a1;
    __syncthreads();
    const float SCALE = 0.08838834764831845f;   // 1/sqrt(128)
    const float LF = 0.14391156831212785f;      // ln(10000)/64
    // q rope: 1024 pairs, 2 per thread
    #pragma unroll
    for (int r = 0; r < 2; ++r) {
        int pi = tid + r * 512;
        int h = pi >> 6, i = pi & 63;
        float ang = (float)pos * expf(-(float)i * LF);
        float c, s; sincosf(ang, &s, &c);
        float x1 = sh[h*128 + i], x2 = sh[h*128 + i + 64];
        g_q[h*128 + i]      = (x1*c - x2*s) * SCALE;
        g_q[h*128 + i + 64] = (x2*c + x1*s) * SCALE;
    }
    // k rope + v: 512 pairs, 1 per thread; publish + cache write
    {
        int kv = tid >> 6, i = tid & 63;
        float ang = (float)pos * expf(-(float)i * LF);
        float c, s; sincosf(ang, &s, &c);
        float k1 = sh[2048 + kv*128 + i], k2 = sh[2048 + kv*128 + i + 64];
        float kr1 = k1*c - k2*s;
        float kr2 = k2*c + k1*s;
        float v1 = sh[3072 + kv*128 + i];
        float v2 = sh[3072 + kv*128 + i + 64];
        g_knew[kv][i]      = kr1;
        g_knew[kv][i + 64] = kr2;
        g_vnew[kv][i]      = v1;
        g_vnew[kv][i + 64] = v2;
        long rb = (((long)layer * NKV + kv) * SEQ + pos) * DH;
        ok[rb + i]      = kr1;
        ok[rb + i + 64] = kr2;
        ov[rb + i]      = v1;
        ov[rb + i + 64] = v2;
    }
}

// ---------------- attention: split-S flash-decode ----------------
// grid (NCH chunks of 128, NKV), 256 thr. Reads K/V from the INPUT caches
// (aligned); row pos comes from g_knew/g_vnew via shared memory.
__global__ void __launch_bounds__(256) k_attn(
    const float* __restrict__ pk, const float* __restrict__ pv,
    const int* __restrict__ stepp, const int* __restrict__ plen, int layer)
{
    __shared__ __align__(16) float sh_q[2][DH];
    __shared__ __align__(16) float sh_k[DH];
    __shared__ __align__(16) float sh_v[DH];
    __shared__ float sh_s[2][128];
    __shared__ float red[8];
    __shared__ float sh_m[2];
    int pos = stepp[0] + plen[0];
    int kv = blockIdx.y, ch = blockIdx.x;
    int s0 = ch << 7;
    int tid = threadIdx.x;
    if (s0 > pos) {
        if (tid < 2) g_attn_l[kv][ch][tid] = 0.f;
        return;
    }
    int smax = min(pos, s0 + 127);
    bool haspos = (ch == (pos >> 7));
    {
        int h = tid >> 7, d = tid & 127;
        sh_q[h][d] = g_q[(kv*2 + h)*DH + d];
        if (haspos) {
            if (tid < 128) sh_k[tid] = g_knew[kv][tid];
            else           sh_v[tid - 128] = g_vnew[kv][tid - 128];
        }
    }
    __syncthreads();
    int warp = tid >> 5, lane = tid & 31;
    float4 q0 = ((const float4*)sh_q[0])[lane];
    float4 q1 = ((const float4*)sh_q[1])[lane];
    long kb = ((long)layer * NKV + kv) * SEQ * DH;
    #pragma unroll 2
    for (int it = 0; it < 16; ++it) {
        int sl = (it << 3) + warp;
        int si = s0 + sl;
        if (si <= smax) {
            float4 kk;
            if (si == pos) kk = ((const float4*)sh_k)[lane];
            else           kk = *(const float4*)(pk + kb + (long)si*DH + lane*4);
            float d0 = q0.x*kk.x + q0.y*kk.y + q0.z*kk.z + q0.w*kk.w;
            float d1 = q1.x*kk.x + q1.y*kk.y + q1.z*kk.z + q1.w*kk.w;
            #pragma unroll
            for (int o = 16; o > 0; o >>= 1) {
                d0 += __shfl_down_sync(0xffffffffu, d0, o);
                d1 += __shfl_down_sync(0xffffffffu, d1, o);
            }
            if (lane == 0) { sh_s[0][sl] = d0; sh_s[1][sl] = d1; }
        } else if (lane == 0) {
            sh_s[0][sl] = -1e30f; sh_s[1][sl] = -1e30f;
        }
    }
    __syncthreads();
    // softmax: thread t -> h = t>>7, idx d = t&127
    int h = tid >> 7, d = tid & 127;
    float v = sh_s[h][d];
    float m = v;
    #pragma unroll
    for (int o = 16; o > 0; o >>= 1) m = fmaxf(m, __shfl_down_sync(0xffffffffu, m, o));
    if (lane == 0) red[warp] = m;
    __syncthreads();
    if (tid < 2)
        sh_m[tid] = fmaxf(fmaxf(red[tid*4], red[tid*4+1]), fmaxf(red[tid*4+2], red[tid*4+3]));
    __syncthreads();
    float p = expf(v - sh_m[h]);
    sh_s[h][d] = p;
    float l = p;
    #pragma unroll
    for (int o = 16; o > 0; o >>= 1) l += __shfl_down_sync(0xffffffffu, l, o);
    if (lane == 0) red[warp] = l;
    __syncthreads();
    if (tid < 2) {
        g_attn_m[kv][ch][tid] = sh_m[tid];
        g_attn_l[kv][ch][tid] = red[tid*4] + red[tid*4+1] + red[tid*4+2] + red[tid*4+3];
    }
    // AV: global rows from input cache, pos row from sh_v
    int count = smax - s0 + 1;
    int nglob = haspos ? count - 1 : count;
    const float* pvp = pv + kb + (long)s0*DH + d;
    float acc = 0.f;
    int s = 0;
    for (; s + 7 < nglob; s += 8) {
        float acc2 = 0.f;
        #pragma unroll
        for (int u = 0; u < 8; u += 2) {
            acc  += sh_s[h][s+u]   * pvp[(long)(s+u)*DH];
            acc2 += sh_s[h][s+u+1] * pvp[(long)(s+u+1)*DH];
        }
        acc += acc2;
    }
    for (; s < nglob; ++s) acc += sh_s[h][s] * pvp[(long)s*DH];
    if (haspos) acc += sh_s[h][count - 1] * sh_v[d];
    g_attn_o[kv][ch][h][d] = acc;
}

// ---------------- Wo GEMV (with split-softmax combine) ----------------
// grid NPO (rowslices of 32; each inside one head), 256 thr.
__global__ void __launch_bounds__(256) k_wo(const float* __restrict__ Wo)
{
    __shared__ float sh_a[32];
    __shared__ float sh_w[NCH];
    __shared__ float sh_ml[2*NCH];
    __shared__ float sh_iden;
    int by = blockIdx.x;
    int r0 = by * 32;
    int p = r0 >> 7, kv = p >> 1, hh = p & 1, db = r0 & 127;
    int tid = threadIdx.x;
    if (tid < NCH) {
        sh_ml[tid]       = g_attn_m[kv][tid][hh];
        sh_ml[NCH + tid] = g_attn_l[kv][tid][hh];
    }
    __syncthreads();
    if (tid == 0) {
        float M = -1e30f;
        for (int c = 0; c < NCH; ++c) if (sh_ml[NCH+c] > 0.f) M = fmaxf(M, sh_ml[c]);
        float den = 0.f;
        for (int c = 0; c < NCH; ++c) {
            float w = (sh_ml[NCH+c] > 0.f) ? expf(sh_ml[c] - M) : 0.f;
            sh_w[c] = w; den += w * sh_ml[NCH+c];
        }
        sh_iden = 1.f / den;
    }
    __syncthreads();
    if (tid < 32) {
        float num = 0.f;
        #pragma unroll
        for (int c = 0; c < NCH; ++c) {
            float w = sh_w[c];
            if (w != 0.f) num += w * g_attn_o[kv][c][hh][db + tid];
        }
        sh_a[tid] = num * sh_iden;
    }
    __syncthreads();
    int j = tid * 4;
    const float* pw = Wo + (long)r0 * DM + j;
    float4 acc = {0.f,0.f,0.f,0.f};
    #pragma unroll 8
    for (int r = 0; r < 32; ++r) {
        float a = sh_a[r];
        float4 w = *(const float4*)(pw + (long)r * DM);
        fma4(acc, a, w);
    }
    *(float4*)&g_o_part[by][j] = acc;
}

// ---------------- gate/up GEMV ----------------
// grid (8 coltiles of 1024, NPG rowslices of 32), 256 thr.
__global__ void __launch_bounds__(256) k_gateup(
    const float* __restrict__ Wg, const float* __restrict__ Wu)
{
    __shared__ float sh_n[32];
    int tid = threadIdx.x;
    int r0 = blockIdx.y * 32;
    if (tid < 32) sh_n[tid] = g_n[r0 + tid];
    __syncthreads();
    int j = blockIdx.x * 1024 + tid * 4;
    const float* W; int jj;
    if (j < FF) { W = Wg; jj = j; } else { W = Wu; jj = j - FF; }
    const float* p = W + (long)r0 * FF + jj;
    float4 acc = {0.f,0.f,0.f,0.f};
    #pragma unroll 8
    for (int r = 0; r < 32; ++r) {
        float a = sh_n[r];
        float4 w = *(const float4*)p;
        fma4(acc, a, w);
        p += FF;
    }
    *(float4*)&g_gu_part[blockIdx.y][j] = acc;
}

// ---------------- Wd GEMV (silu combine inline) ----------------
// grid NPD (rowslices of 64), 256 thr.
__global__ void __launch_bounds__(256) k_wd(const float* __restrict__ Wd)
{
    __shared__ float sh_h[64];
    int by = blockIdx.x;
    int r0 = by * 64;
    int tid = threadIdx.x;
    if (tid < 64) {
        float g = 0.f, u = 0.f;
        #pragma unroll
        for (int i = 0; i < NPG; ++i) {
            g += g_gu_part[i][r0 + tid];
            u += g_gu_part[i][FF + r0 + tid];
        }
        sh_h[tid] = (g / (1.f + expf(-g))) * u;
    }
    __syncthreads();
    int j = tid * 4;
    const float* pw = Wd + (long)r0 * DM + j;
    float4 acc = {0.f,0.f,0.f,0.f};
    #pragma unroll 8
    for (int r = 0; r < 64; ++r) {
        float a = sh_h[r];
        float4 w = *(const float4*)(pw + (long)r * DM);
        fma4(acc, a, w);
    }
    *(float4*)&g_d_part[by][j] = acc;
}

// ---------------- LM head GEMV ----------------
// grid (32 coltiles of 1024, NPL rowslices of 128), 256 thr.
__global__ void __launch_bounds__(256) k_lm(const float* __restrict__ Wlm)
{
    __shared__ float sh_n[128];
    int tid = threadIdx.x;
    int r0 = blockIdx.y * 128;
    if (tid < 128) sh_n[tid] = g_n[r0 + tid];
    __syncthreads();
    int j = blockIdx.x * 1024 + tid * 4;
    if (j >= VOC) return;
    const float* p = Wlm + (long)r0 * VOC + j;
    float4 acc = {0.f,0.f,0.f,0.f};
    #pragma unroll 8
    for (int r = 0; r < 128; ++r) {
        float a = sh_n[r];
        float4 w = *(const float4*)p;
        fma4(acc, a, w);
        p += VOC;
    }
    *(float4*)&g_lm_part[blockIdx.y][j] = acc;
}

// ---------------- argmax ----------------
__global__ void __launch_bounds__(256) k_amax1()
{
    __shared__ float sv[256];
    __shared__ int   si[256];
    int t = threadIdx.x;
    int j = blockIdx.x * 256 + t;
    float v = 0.f;
    #pragma unroll
    for (int i = 0; i < NPL; ++i) v += g_lm_part[i][j];
    sv[t] = v; si[t] = j;
    __syncthreads();
    for (int o = 128; o > 0; o >>= 1) {
        if (t < o) {
            float v2 = sv[t + o]; int i2 = si[t + o];
            if (v2 > sv[t] || (v2 == sv[t] && i2 < si[t])) { sv[t] = v2; si[t] = i2; }
        }
        __syncthreads();
    }
    if (t == 0) { g_amax_val[blockIdx.x] = sv[0]; g_amax_idx[blockIdx.x] = si[0]; }
}

__global__ void __launch_bounds__(128) k_amax2(float* __restrict__ out)
{
    __shared__ float sv[128];
    __shared__ int   si[128];
    int t = threadIdx.x;
    if (t < 125) { sv[t] = g_amax_val[t]; si[t] = g_amax_idx[t]; }
    else         { sv[t] = -1e38f;        si[t] = 0x7fffffff; }
    __syncthreads();
    for (int o = 64; o > 0; o >>= 1) {
        if (t < o) {
            float v2 = sv[t + o]; int i2 = si[t + o];
            if (v2 > sv[t] || (v2 == sv[t] && i2 < si[t])) { sv[t] = v2; si[t] = i2; }
        }
        __syncthreads();
    }
    if (t == 0) out[0] = (float)si[0];
}

// ---------------- launch ----------------
extern "C" void kernel_launch(void* const* d_in, const int* in_sizes, int n_in,
                              void* d_out, int out_size)
{
    const int*   ids  = (const int*)  d_in[0];
    const int*   step = (const int*)  d_in[1];
    const int*   plen = (const int*)  d_in[2];
    const float* pk   = (const float*)d_in[3];
    const float* pv   = (const float*)d_in[4];
    const float* emb  = (const float*)d_in[5];
    const float* Wq   = (const float*)d_in[6];
    const float* Wk   = (const float*)d_in[7];
    const float* Wv   = (const float*)d_in[8];
    const float* Wo   = (const float*)d_in[9];
    const float* Wg   = (const float*)d_in[10];
    const float* Wu   = (const float*)d_in[11];
    const float* Wd   = (const float*)d_in[12];
    const float* ln1  = (const float*)d_in[13];
    const float* ln2  = (const float*)d_in[14];
    const float* lnf  = (const float*)d_in[15];
    const float* Wlm  = (const float*)d_in[16];

    float* out = (float*)d_out;
    const long CACHE = (long)NL * NKV * SEQ * DH;
    float* ok = out + 1;
    float* ov = out + 1 + CACHE;

    k_copy<<<2048, 256>>>(pk, pv, ok, ov);

    for (int l = 0; l < NL; ++l) {
        k_rn<<<1, 256>>>(ln1 + (long)l * DM, l == 0 ? 0 : 1, emb, ids);
        k_qkv<<<dim3(4, NPQ), 256>>>(
            Wq + (long)l * DM * NH * DH,
            Wk + (long)l * DM * NKV * DH,
            Wv + (long)l * DM * NKV * DH);
        k_qkvr<<<1, 512>>>(step, plen, l, ok, ov);
        k_attn<<<dim3(NCH, NKV), 256>>>(pk, pv, step, plen, l);
        k_wo<<<NPO, 256>>>(Wo + (long)l * NH * DH * DM);
        k_rn<<<1, 256>>>(ln2 + (long)l * DM, 2, nullptr, nullptr);
        k_gateup<<<dim3(8, NPG), 256>>>(
            Wg + (long)l * DM * FF,
            Wu + (long)l * DM * FF);
        k_wd<<<NPD, 256>>>(Wd + (long)l * FF * DM);
    }

    k_rn<<<1, 256>>>(lnf, 1, nullptr, nullptr);
    k_lm<<<dim3(32, NPL), 256>>>(Wlm);
    k_amax1<<<125, 256>>>();
    k_amax2<<<1, 128>>>(out);
}